// round 1
// baseline (speedup 1.0000x reference)
#include <cuda_runtime.h>
#include <cuda_bf16.h>

// Attention with elementwise scale matrix:
//   S = (Q K^T) * scale  ;  P = softmax_row(S)  ;  O = P V
// B=16, S=2048, D=128, fp32. Fused flash-attention style, fp32 CUDA cores.

#define BATCH 16
#define SEQ   2048
#define DIM   128
#define BM    64
#define BN    64
#define NTHREADS 256

__global__ __launch_bounds__(NTHREADS, 1)
void fa_scale_kernel(const float* __restrict__ Q,
                     const float* __restrict__ K,
                     const float* __restrict__ V,
                     const float* __restrict__ scale,
                     float* __restrict__ O)
{
    extern __shared__ float smem[];
    float* Qs = smem;                 // [BM][DIM]      32 KB (no swizzle; broadcast reads)
    float* Ks = Qs + BM * DIM;        // [BN][DIM]      32 KB (XOR-swizzled float4 columns)
    float* Vs = Ks + BN * DIM;        // [BN][DIM]      32 KB (row-major)
    float* Ps = Vs + BN * DIM;        // [BM][BN]       16 KB (probabilities)

    const int tid = threadIdx.x;
    const int tx  = tid & 15;         // 0..15  -> key cols / dim cols
    const int ty  = tid >> 4;         // 0..15  -> query rows (4 per thread)
    const int q0  = blockIdx.x * BM;
    const int b   = blockIdx.y;

    const float* Qb = Q + (size_t)b * SEQ * DIM;
    const float* Kb = K + (size_t)b * SEQ * DIM;
    const float* Vb = V + (size_t)b * SEQ * DIM;

    // ---- load Q tile once (coalesced float4) ----
    for (int idx = tid; idx < BM * (DIM / 4); idx += NTHREADS) {
        int n = idx >> 5, c = idx & 31;
        *(float4*)(Qs + n * DIM + c * 4) =
            *(const float4*)(Qb + (size_t)(q0 + n) * DIM + c * 4);
    }

    float m_i[4], l_i[4], o_acc[4][8];
    #pragma unroll
    for (int i = 0; i < 4; i++) {
        m_i[i] = -1e30f; l_i[i] = 0.f;
        #pragma unroll
        for (int j = 0; j < 8; j++) o_acc[i][j] = 0.f;
    }

    const int row0 = ty * 4;          // first of 4 query rows owned by this thread

    for (int kt = 0; kt < SEQ / BN; kt++) {
        const int k0 = kt * BN;

        __syncthreads();   // prior PV reads of Ks/Vs done before overwrite (noop on iter 0 wrt loads)

        // ---- load K tile (XOR swizzle on float4 column index) and V tile ----
        for (int idx = tid; idx < BN * (DIM / 4); idx += NTHREADS) {
            int n = idx >> 5, c = idx & 31;
            float4 kv = *(const float4*)(Kb + (size_t)(k0 + n) * DIM + c * 4);
            int cs = c ^ ((n >> 2) & 7);
            *(float4*)(Ks + n * DIM + cs * 4) = kv;
            *(float4*)(Vs + n * DIM + c * 4) =
                *(const float4*)(Vb + (size_t)(k0 + n) * DIM + c * 4);
        }
        __syncthreads();

        // ---- S tile: s[i][j] = Q[row0+i] . K[tx*4+j] ----
        float s[4][4];
        #pragma unroll
        for (int i = 0; i < 4; i++)
            #pragma unroll
            for (int j = 0; j < 4; j++) s[i][j] = 0.f;

        #pragma unroll 8
        for (int k4 = 0; k4 < DIM / 4; k4++) {
            float4 a[4], bb[4];
            #pragma unroll
            for (int i = 0; i < 4; i++)
                a[i] = *(const float4*)(Qs + (row0 + i) * DIM + k4 * 4);
            const int bc = (k4 ^ (tx & 7)) * 4;   // un-swizzle (same for all j: j only in low 2 bits of n)
            #pragma unroll
            for (int j = 0; j < 4; j++)
                bb[j] = *(const float4*)(Ks + (tx * 4 + j) * DIM + bc);
            #pragma unroll
            for (int i = 0; i < 4; i++)
                #pragma unroll
                for (int j = 0; j < 4; j++) {
                    s[i][j] = fmaf(a[i].x, bb[j].x, s[i][j]);
                    s[i][j] = fmaf(a[i].y, bb[j].y, s[i][j]);
                    s[i][j] = fmaf(a[i].z, bb[j].z, s[i][j]);
                    s[i][j] = fmaf(a[i].w, bb[j].w, s[i][j]);
                }
        }

        // ---- elementwise scale + online softmax (row reductions across 16 lanes) ----
        #pragma unroll
        for (int i = 0; i < 4; i++) {
            const int rg = q0 + row0 + i;
            float4 sc = *(const float4*)(scale + (size_t)rg * SEQ + k0 + tx * 4);
            s[i][0] *= sc.x; s[i][1] *= sc.y; s[i][2] *= sc.z; s[i][3] *= sc.w;

            float mx = fmaxf(fmaxf(s[i][0], s[i][1]), fmaxf(s[i][2], s[i][3]));
            #pragma unroll
            for (int msk = 8; msk >= 1; msk >>= 1)
                mx = fmaxf(mx, __shfl_xor_sync(0xffffffffu, mx, msk));

            float m_new = fmaxf(m_i[i], mx);
            float alpha = __expf(m_i[i] - m_new);
            float sum = 0.f;
            #pragma unroll
            for (int j = 0; j < 4; j++) {
                float p = __expf(s[i][j] - m_new);
                s[i][j] = p; sum += p;
            }
            #pragma unroll
            for (int msk = 8; msk >= 1; msk >>= 1)
                sum += __shfl_xor_sync(0xffffffffu, sum, msk);

            l_i[i] = l_i[i] * alpha + sum;
            m_i[i] = m_new;
            #pragma unroll
            for (int j = 0; j < 8; j++) o_acc[i][j] *= alpha;

            *(float4*)(Ps + (row0 + i) * BN + tx * 4) =
                make_float4(s[i][0], s[i][1], s[i][2], s[i][3]);
        }
        // P row r is written and read entirely by the 16 threads of one warp-half (same ty)
        __syncwarp();

        // ---- O += P V  (thread owns rows row0..row0+3, cols tx*4..+3 and 64+tx*4..+3) ----
        #pragma unroll 4
        for (int kk = 0; kk < BN; kk++) {
            float p[4];
            #pragma unroll
            for (int i = 0; i < 4; i++) p[i] = Ps[(row0 + i) * BN + kk];
            float4 v0 = *(const float4*)(Vs + kk * DIM + tx * 4);
            float4 v1 = *(const float4*)(Vs + kk * DIM + 64 + tx * 4);
            #pragma unroll
            for (int i = 0; i < 4; i++) {
                o_acc[i][0] = fmaf(p[i], v0.x, o_acc[i][0]);
                o_acc[i][1] = fmaf(p[i], v0.y, o_acc[i][1]);
                o_acc[i][2] = fmaf(p[i], v0.z, o_acc[i][2]);
                o_acc[i][3] = fmaf(p[i], v0.w, o_acc[i][3]);
                o_acc[i][4] = fmaf(p[i], v1.x, o_acc[i][4]);
                o_acc[i][5] = fmaf(p[i], v1.y, o_acc[i][5]);
                o_acc[i][6] = fmaf(p[i], v1.z, o_acc[i][6]);
                o_acc[i][7] = fmaf(p[i], v1.w, o_acc[i][7]);
            }
        }
    }

    // ---- epilogue: normalize + write ----
    #pragma unroll
    for (int i = 0; i < 4; i++) {
        float inv = 1.f / l_i[i];
        size_t row = (size_t)b * SEQ + q0 + row0 + i;
        float4 r0 = make_float4(o_acc[i][0] * inv, o_acc[i][1] * inv,
                                o_acc[i][2] * inv, o_acc[i][3] * inv);
        float4 r1 = make_float4(o_acc[i][4] * inv, o_acc[i][5] * inv,
                                o_acc[i][6] * inv, o_acc[i][7] * inv);
        *(float4*)(O + row * DIM + tx * 4)      = r0;
        *(float4*)(O + row * DIM + 64 + tx * 4) = r1;
    }
}

extern "C" void kernel_launch(void* const* d_in, const int* in_sizes, int n_in,
                              void* d_out, int out_size)
{
    const float* Q     = (const float*)d_in[0];
    const float* K     = (const float*)d_in[1];
    const float* V     = (const float*)d_in[2];
    const float* scale = (const float*)d_in[3];
    // d_in[4] = dropout_p (== 0, ignored)
    float* O = (float*)d_out;

    const int smem_bytes = (3 * BM * DIM + BM * BN) * (int)sizeof(float); // 114688
    cudaFuncSetAttribute(fa_scale_kernel,
                         cudaFuncAttributeMaxDynamicSharedMemorySize, smem_bytes);

    dim3 grid(SEQ / BM, BATCH);
    fa_scale_kernel<<<grid, NTHREADS, smem_bytes>>>(Q, K, V, scale, O);
}

// round 3
// speedup vs baseline: 2.6158x; 2.6158x over previous
#include <cuda_runtime.h>
#include <cuda_bf16.h>
#include <cstdint>

#define BATCH 16
#define SEQ   2048
#define DIM   128
#define BM    128
#define BN    64
#define KTILES (SEQ / BN)
#define NTHREADS 256

// SMEM byte offsets. bf16 tiles use padded row stride 136 bf16 = 272 B
// (row starts shift by 4 banks -> ldmatrix conflict-free, 16B aligned).
#define QSTRIDE 272
#define SM_Q_HI 0
#define SM_Q_LO (SM_Q_HI + 128 * QSTRIDE)      // 34816
#define SM_K_HI (SM_Q_LO + 128 * QSTRIDE)      // 69632
#define SM_K_LO (SM_K_HI + 64 * QSTRIDE)       // 87040
#define SM_V_HI (SM_K_LO + 64 * QSTRIDE)       // 104448
#define SM_V_LO (SM_V_HI + 64 * QSTRIDE)       // 121856
#define SM_SC   (SM_V_LO + 64 * QSTRIDE)       // 139264 ; scale [128][68] f32
#define SM_TOTAL (SM_SC + 128 * 68 * 4)        // 174080

__device__ __forceinline__ uint32_t smem_u32(const void* p) {
    uint32_t a;
    asm("{ .reg .u64 t; cvta.to.shared.u64 t, %1; cvt.u32.u64 %0, t; }" : "=r"(a) : "l"(p));
    return a;
}
__device__ __forceinline__ void ldsm_x4(uint32_t* r, uint32_t a) {
    asm volatile("ldmatrix.sync.aligned.m8n8.x4.shared.b16 {%0,%1,%2,%3}, [%4];"
        : "=r"(r[0]), "=r"(r[1]), "=r"(r[2]), "=r"(r[3]) : "r"(a));
}
__device__ __forceinline__ void ldsm_x4_t(uint32_t* r, uint32_t a) {
    asm volatile("ldmatrix.sync.aligned.m8n8.x4.trans.shared.b16 {%0,%1,%2,%3}, [%4];"
        : "=r"(r[0]), "=r"(r[1]), "=r"(r[2]), "=r"(r[3]) : "r"(a));
}
__device__ __forceinline__ void mma_bf16(float* c, const uint32_t* a, uint32_t b0, uint32_t b1) {
    asm volatile("mma.sync.aligned.m16n8k16.row.col.f32.bf16.bf16.f32 "
        "{%0,%1,%2,%3}, {%4,%5,%6,%7}, {%8,%9}, {%0,%1,%2,%3};"
        : "+f"(c[0]), "+f"(c[1]), "+f"(c[2]), "+f"(c[3])
        : "r"(a[0]), "r"(a[1]), "r"(a[2]), "r"(a[3]), "r"(b0), "r"(b1));
}
__device__ __forceinline__ uint32_t pack_bf16(float lo, float hi) {
    __nv_bfloat162 t = __floats2bfloat162_rn(lo, hi);
    return *reinterpret_cast<uint32_t*>(&t);
}
// split a float4 into packed bf16 hi words and lo (residual) words
__device__ __forceinline__ void cvt_split(float4 v, uint2& hi, uint2& lo) {
    __nv_bfloat162 h01 = __floats2bfloat162_rn(v.x, v.y);
    __nv_bfloat162 h23 = __floats2bfloat162_rn(v.z, v.w);
    float rx = v.x - __bfloat162float(h01.x);
    float ry = v.y - __bfloat162float(h01.y);
    float rz = v.z - __bfloat162float(h23.x);
    float rw = v.w - __bfloat162float(h23.y);
    __nv_bfloat162 l01 = __floats2bfloat162_rn(rx, ry);
    __nv_bfloat162 l23 = __floats2bfloat162_rn(rz, rw);
    hi = make_uint2(*reinterpret_cast<uint32_t*>(&h01), *reinterpret_cast<uint32_t*>(&h23));
    lo = make_uint2(*reinterpret_cast<uint32_t*>(&l01), *reinterpret_cast<uint32_t*>(&l23));
}
// FFMA-pipe exp (no MUFU), valid for x <= 0
__device__ __forceinline__ float fexp(float x) {
    float t = fmaxf(x * 1.4426950408889634f, -126.0f);
    float z = __fadd_rn(t, 12582912.0f);
    int   n = __float_as_int(z) - 0x4B400000;
    float f = t - (z - 12582912.0f);
    float p = 0.0013333558f;
    p = fmaf(p, f, 0.0096181291f);
    p = fmaf(p, f, 0.0555041086f);
    p = fmaf(p, f, 0.2402265069f);
    p = fmaf(p, f, 0.6931471806f);
    p = fmaf(p, f, 1.0f);
    return __int_as_float(__float_as_int(p) + (n << 23));
}

__global__ __launch_bounds__(NTHREADS, 1)
void attn_mma_kernel(const float* __restrict__ Q, const float* __restrict__ K,
                     const float* __restrict__ V, const float* __restrict__ scale,
                     float* __restrict__ Out)
{
    extern __shared__ char smem[];
    const uint32_t sb = smem_u32(smem);
    float* scs = (float*)(smem + SM_SC);

    const int tid  = threadIdx.x;
    const int wid  = tid >> 5;
    const int lane = tid & 31;
    const int g    = lane >> 2;      // 0..7
    const int t4   = lane & 3;       // 0..3
    const int wr   = wid * 16;       // warp's q-row base within tile
    const int q0   = blockIdx.x * BM;
    const int b    = blockIdx.y;

    const float* Qb = Q + (size_t)b * SEQ * DIM;
    const float* Kb = K + (size_t)b * SEQ * DIM;
    const float* Vb = V + (size_t)b * SEQ * DIM;

    // ---- stage Q tile once: f32 -> bf16 hi/lo ----
    for (int i = tid; i < 128 * 32; i += NTHREADS) {
        int r = i >> 5, c4 = i & 31;
        float4 v = *(const float4*)(Qb + (size_t)(q0 + r) * DIM + c4 * 4);
        uint2 hi, lo; cvt_split(v, hi, lo);
        *(uint2*)(smem + SM_Q_HI + r * QSTRIDE + c4 * 8) = hi;
        *(uint2*)(smem + SM_Q_LO + r * QSTRIDE + c4 * 8) = lo;
    }

    // per-lane ldmatrix base offsets
    const uint32_t qa_off = (uint32_t)((wr + (lane & 7) + ((lane >> 3) & 1) * 8) * QSTRIDE
                                       + ((lane >> 4) & 1) * 16);
    const uint32_t kb_row = (uint32_t)((lane & 7) + ((lane >> 4) & 1) * 8);
    const uint32_t kb_col = (uint32_t)(((lane >> 3) & 1) * 16);
    const uint32_t v_row  = (uint32_t)(lane & 15);
    const uint32_t v_col  = (uint32_t)(((lane >> 4) & 1) * 16);

    float o[16][4];
    #pragma unroll
    for (int j = 0; j < 16; j++)
        { o[j][0] = 0.f; o[j][1] = 0.f; o[j][2] = 0.f; o[j][3] = 0.f; }
    float m0 = -1e30f, m1 = -1e30f, l0 = 0.f, l1 = 0.f;

    for (int kt = 0; kt < KTILES; kt++) {
        const int k0 = kt * BN;
        __syncthreads();   // previous iteration's reads of K/V/scale complete

        // ---- stage K, V (bf16 hi/lo) and scale tile ----
        for (int i = tid; i < 64 * 32; i += NTHREADS) {
            int r = i >> 5, c4 = i & 31;
            float4 kv = *(const float4*)(Kb + (size_t)(k0 + r) * DIM + c4 * 4);
            float4 vv = *(const float4*)(Vb + (size_t)(k0 + r) * DIM + c4 * 4);
            uint2 hi, lo;
            cvt_split(kv, hi, lo);
            *(uint2*)(smem + SM_K_HI + r * QSTRIDE + c4 * 8) = hi;
            *(uint2*)(smem + SM_K_LO + r * QSTRIDE + c4 * 8) = lo;
            cvt_split(vv, hi, lo);
            *(uint2*)(smem + SM_V_HI + r * QSTRIDE + c4 * 8) = hi;
            *(uint2*)(smem + SM_V_LO + r * QSTRIDE + c4 * 8) = lo;
        }
        for (int i = tid; i < 128 * 16; i += NTHREADS) {
            int r = i >> 4, c4 = i & 15;
            float4 v = *(const float4*)(scale + (size_t)(q0 + r) * SEQ + k0 + c4 * 4);
            *(float4*)(scs + r * 68 + c4 * 4) = v;
        }
        __syncthreads();

        // ---- S = (Q K^T) via bf16 3-product split ----
        float s[8][4];
        #pragma unroll
        for (int j = 0; j < 8; j++)
            { s[j][0] = 0.f; s[j][1] = 0.f; s[j][2] = 0.f; s[j][3] = 0.f; }

        #pragma unroll
        for (int kc = 0; kc < 8; kc++) {
            uint32_t ah[4], al[4];
            ldsm_x4(ah, sb + SM_Q_HI + qa_off + kc * 32);
            ldsm_x4(al, sb + SM_Q_LO + qa_off + kc * 32);
            #pragma unroll
            for (int jp = 0; jp < 4; jp++) {
                uint32_t boff = (16 * jp + kb_row) * QSTRIDE + kc * 32 + kb_col;
                uint32_t bh[4], bl[4];
                ldsm_x4(bh, sb + SM_K_HI + boff);
                ldsm_x4(bl, sb + SM_K_LO + boff);
                mma_bf16(s[2*jp],   ah, bh[0], bh[1]);
                mma_bf16(s[2*jp],   ah, bl[0], bl[1]);
                mma_bf16(s[2*jp],   al, bh[0], bh[1]);
                mma_bf16(s[2*jp+1], ah, bh[2], bh[3]);
                mma_bf16(s[2*jp+1], ah, bl[2], bl[3]);
                mma_bf16(s[2*jp+1], al, bh[2], bh[3]);
            }
        }

        // ---- scale multiply + online softmax (rows wr+g and wr+g+8) ----
        const float* sc0 = scs + (wr + g) * 68;
        const float* sc1 = sc0 + 8 * 68;
        float mx0 = -1e30f, mx1 = -1e30f;
        #pragma unroll
        for (int j = 0; j < 8; j++) {
            float2 a = *(const float2*)(sc0 + 8 * j + 2 * t4);
            float2 c = *(const float2*)(sc1 + 8 * j + 2 * t4);
            s[j][0] *= a.x; s[j][1] *= a.y;
            s[j][2] *= c.x; s[j][3] *= c.y;
            mx0 = fmaxf(mx0, fmaxf(s[j][0], s[j][1]));
            mx1 = fmaxf(mx1, fmaxf(s[j][2], s[j][3]));
        }
        mx0 = fmaxf(mx0, __shfl_xor_sync(0xffffffffu, mx0, 1));
        mx0 = fmaxf(mx0, __shfl_xor_sync(0xffffffffu, mx0, 2));
        mx1 = fmaxf(mx1, __shfl_xor_sync(0xffffffffu, mx1, 1));
        mx1 = fmaxf(mx1, __shfl_xor_sync(0xffffffffu, mx1, 2));

        float mn0 = fmaxf(m0, mx0), mn1 = fmaxf(m1, mx1);
        float a0 = fexp(m0 - mn0),  a1 = fexp(m1 - mn1);
        float sum0 = 0.f, sum1 = 0.f;
        #pragma unroll
        for (int j = 0; j < 8; j++) {
            s[j][0] = fexp(s[j][0] - mn0); sum0 += s[j][0];
            s[j][1] = fexp(s[j][1] - mn0); sum0 += s[j][1];
            s[j][2] = fexp(s[j][2] - mn1); sum1 += s[j][2];
            s[j][3] = fexp(s[j][3] - mn1); sum1 += s[j][3];
        }
        sum0 += __shfl_xor_sync(0xffffffffu, sum0, 1);
        sum0 += __shfl_xor_sync(0xffffffffu, sum0, 2);
        sum1 += __shfl_xor_sync(0xffffffffu, sum1, 1);
        sum1 += __shfl_xor_sync(0xffffffffu, sum1, 2);
        l0 = l0 * a0 + sum0; m0 = mn0;
        l1 = l1 * a1 + sum1; m1 = mn1;
        #pragma unroll
        for (int j = 0; j < 16; j++) {
            o[j][0] *= a0; o[j][1] *= a0;
            o[j][2] *= a1; o[j][3] *= a1;
        }

        // ---- O += P V via bf16 3-product split ----
        #pragma unroll
        for (int c = 0; c < 4; c++) {
            // P fragment (A, m16k16) for keys 16c..16c+15 from S tiles 2c, 2c+1
            uint32_t ph[4], pl[4];
            {
                float p00 = s[2*c][0],   p01 = s[2*c][1];
                float p02 = s[2*c][2],   p03 = s[2*c][3];
                float p10 = s[2*c+1][0], p11 = s[2*c+1][1];
                float p12 = s[2*c+1][2], p13 = s[2*c+1][3];
                __nv_bfloat162 h;
                float r0, r1;
                h = __floats2bfloat162_rn(p00, p01); ph[0] = *(uint32_t*)&h;
                r0 = p00 - __bfloat162float(h.x); r1 = p01 - __bfloat162float(h.y);
                pl[0] = pack_bf16(r0, r1);
                h = __floats2bfloat162_rn(p02, p03); ph[1] = *(uint32_t*)&h;
                r0 = p02 - __bfloat162float(h.x); r1 = p03 - __bfloat162float(h.y);
                pl[1] = pack_bf16(r0, r1);
                h = __floats2bfloat162_rn(p10, p11); ph[2] = *(uint32_t*)&h;
                r0 = p10 - __bfloat162float(h.x); r1 = p11 - __bfloat162float(h.y);
                pl[2] = pack_bf16(r0, r1);
                h = __floats2bfloat162_rn(p12, p13); ph[3] = *(uint32_t*)&h;
                r0 = p12 - __bfloat162float(h.x); r1 = p13 - __bfloat162float(h.y);
                pl[3] = pack_bf16(r0, r1);
            }
            #pragma unroll
            for (int jp = 0; jp < 8; jp++) {
                uint32_t voff = (16 * c + v_row) * QSTRIDE + (16 * jp) * 2 + v_col;
                uint32_t bh[4], bl[4];
                ldsm_x4_t(bh, sb + SM_V_HI + voff);
                ldsm_x4_t(bl, sb + SM_V_LO + voff);
                mma_bf16(o[2*jp],   ph, bh[0], bh[1]);
                mma_bf16(o[2*jp],   ph, bl[0], bl[1]);
                mma_bf16(o[2*jp],   pl, bh[0], bh[1]);
                mma_bf16(o[2*jp+1], ph, bh[2], bh[3]);
                mma_bf16(o[2*jp+1], ph, bl[2], bl[3]);
                mma_bf16(o[2*jp+1], pl, bh[2], bh[3]);
            }
        }
    }

    // ---- epilogue ----
    float inv0 = 1.f / l0, inv1 = 1.f / l1;
    float* out0 = Out + (size_t)((size_t)b * SEQ + q0 + wr + g) * DIM;
    float* out1 = out0 + 8 * DIM;
    #pragma unroll
    for (int j = 0; j < 16; j++) {
        int col = 8 * j + 2 * t4;
        *(float2*)(out0 + col) = make_float2(o[j][0] * inv0, o[j][1] * inv0);
        *(float2*)(out1 + col) = make_float2(o[j][2] * inv1, o[j][3] * inv1);
    }
}

extern "C" void kernel_launch(void* const* d_in, const int* in_sizes, int n_in,
                              void* d_out, int out_size)
{
    const float* Q     = (const float*)d_in[0];
    const float* K     = (const float*)d_in[1];
    const float* V     = (const float*)d_in[2];
    const float* scale = (const float*)d_in[3];
    float* O = (float*)d_out;

    cudaFuncSetAttribute(attn_mma_kernel,
                         cudaFuncAttributeMaxDynamicSharedMemorySize, SM_TOTAL);
    dim3 grid(SEQ / BM, BATCH);
    attn_mma_kernel<<<grid, NTHREADS, SM_TOTAL>>>(Q, K, V, scale, O);
}